// round 1
// baseline (speedup 1.0000x reference)
#include <cuda_runtime.h>
#include <math.h>

#define BATCH 64
#define LSUB  512
#define SWORDS 512
#define HID   768
#define NC    9
#define NWORDS (BATCH * SWORDS)

// scratch (no cudaMalloc allowed)
__device__ int   g_starts[NWORDS];
__device__ float g_loss;
__device__ int   g_cnt;

// ---------------------------------------------------------------------------
// Kernel A: per-batch exclusive scan of ids_lens -> word start offsets.
// One block (512 threads) per batch. Also zeroes the loss accumulators.
// ---------------------------------------------------------------------------
__global__ void scan_kernel(const int* __restrict__ ids_lens) {
    __shared__ int sh[SWORDS];
    int b = blockIdx.x, t = threadIdx.x;
    int len = ids_lens[b * SWORDS + t];
    sh[t] = len;
    __syncthreads();
#pragma unroll
    for (int off = 1; off < SWORDS; off <<= 1) {
        int v = (t >= off) ? sh[t - off] : 0;
        __syncthreads();
        sh[t] += v;
        __syncthreads();
    }
    g_starts[b * SWORDS + t] = sh[t] - len;   // exclusive prefix = word start
    if (b == 0 && t == 0) { g_loss = 0.0f; g_cnt = 0; }
}

// ---------------------------------------------------------------------------
// Kernel B: main. One warp processes TWO words per iteration (amortizes the
// shared-memory W reads). Per word: register-sum the <=3 subword rows, then
// 9 FMAs per element against W in shared. Warp-reduce 9+9 logit partials,
// lane 0 does log-softmax / argmax / NLL.
// ---------------------------------------------------------------------------
__global__ void __launch_bounds__(512, 2) main_kernel(
    const float* __restrict__ x,       // [B, L, H]
    const float* __restrict__ W,       // [H, C]
    const float* __restrict__ bias,    // [C]
    const int*   __restrict__ ids_lens,// [B, S]
    const int*   __restrict__ label_ids,
    float*       __restrict__ out)     // out[0]=loss (later), out[1..]=pred
{
    __shared__ float Ws[HID * NC];     // 27648 B
    __shared__ float s_loss;
    __shared__ int   s_cnt;

    int tid = threadIdx.x;
    for (int i = tid; i < HID * NC; i += blockDim.x) Ws[i] = W[i];
    if (tid == 0) { s_loss = 0.0f; s_cnt = 0; }
    __syncthreads();

    int lane = tid & 31;
    int warp = tid >> 5;
    int gw   = blockIdx.x * (blockDim.x >> 5) + warp;
    int nw   = gridDim.x * (blockDim.x >> 5);

    float lloss = 0.0f;
    int   lcnt  = 0;

    for (int p = gw; p < NWORDS / 2; p += nw) {
        int w0 = 2 * p, w1 = 2 * p + 1;           // same batch always (w0 even)
        int len0 = ids_lens[w0], len1 = ids_lens[w1];
        int st0  = g_starts[w0], st1 = g_starts[w1];
        int b0   = w0 >> 9;

        const float* base0 = x + ((size_t)(b0 * LSUB + st0)) * HID;
        const float* base1 = x + ((size_t)(b0 * LSUB + st1)) * HID;

        float acc0[NC], acc1[NC];
#pragma unroll
        for (int c = 0; c < NC; c++) { acc0[c] = 0.0f; acc1[c] = 0.0f; }

        for (int h = lane; h < HID; h += 32) {
            float v0 = 0.0f, v1 = 0.0f;
            for (int r = 0; r < len0; r++) v0 += base0[r * HID + h];
            for (int r = 0; r < len1; r++) v1 += base1[r * HID + h];
            const float* wr = &Ws[h * NC];
#pragma unroll
            for (int c = 0; c < NC; c++) {
                float wv = wr[c];                  // conflict-free: bank=(9*lane+c)%32
                acc0[c] = fmaf(v0, wv, acc0[c]);
                acc1[c] = fmaf(v1, wv, acc1[c]);
            }
        }

        // warp tree-reduce the 18 partials
#pragma unroll
        for (int c = 0; c < NC; c++) {
#pragma unroll
            for (int off = 16; off; off >>= 1) {
                acc0[c] += __shfl_xor_sync(0xffffffffu, acc0[c], off);
                acc1[c] += __shfl_xor_sync(0xffffffffu, acc1[c], off);
            }
        }

        if (lane == 0) {
#pragma unroll
            for (int which = 0; which < 2; which++) {
                int   w   = which ? w1 : w0;
                int   len = which ? len1 : len0;
                float* a  = which ? acc1 : acc0;

                float inv = (len > 0) ? (1.0f / (float)len) : 0.0f;
                float lg[NC];
                float m = -1e30f; int am = 0;
#pragma unroll
                for (int c = 0; c < NC; c++) {
                    lg[c] = a[c] * inv + bias[c];  // len==0 -> logits = bias
                    if (lg[c] > m) { m = lg[c]; am = c; }
                }
                out[1 + w] = (float)am;
                if (len > 0) {
                    float sum = 0.0f;
#pragma unroll
                    for (int c = 0; c < NC; c++) sum += expf(lg[c] - m);
                    int lab = label_ids[w];
                    lab = lab < 0 ? 0 : (lab > NC - 1 ? NC - 1 : lab);
                    lloss += -(lg[lab] - m - logf(sum));
                    lcnt  += 1;
                }
            }
        }
    }

    if (lane == 0 && (lcnt > 0)) {
        atomicAdd(&s_loss, lloss);
        atomicAdd(&s_cnt, lcnt);
    }
    __syncthreads();
    if (tid == 0 && s_cnt > 0) {
        atomicAdd(&g_loss, s_loss);
        atomicAdd(&g_cnt, s_cnt);
    }
}

// ---------------------------------------------------------------------------
// Kernel C: finalize loss.
// ---------------------------------------------------------------------------
__global__ void finalize_kernel(float* __restrict__ out) {
    out[0] = g_loss / fmaxf((float)g_cnt, 1.0f);
}

extern "C" void kernel_launch(void* const* d_in, const int* in_sizes, int n_in,
                              void* d_out, int out_size) {
    const float* bert_out  = (const float*)d_in[0];   // [64,512,768]
    const float* W         = (const float*)d_in[1];   // [768,9]
    const float* b         = (const float*)d_in[2];   // [9]
    // d_in[3] = attention_mask (unused: derivable from ids_lens)
    const int*   ids_lens  = (const int*)d_in[4];     // [64,512]
    const int*   label_ids = (const int*)d_in[5];     // [64,512]
    // d_in[6] = label_mask (unused: == ids_lens > 0)
    float* out = (float*)d_out;                       // [1 + 64*512]

    scan_kernel<<<BATCH, SWORDS>>>(ids_lens);
    main_kernel<<<296, 512>>>(bert_out, W, b, ids_lens, label_ids, out);
    finalize_kernel<<<1, 1>>>(out);
}

// round 2
// speedup vs baseline: 3.3108x; 3.3108x over previous
#include <cuda_runtime.h>
#include <math.h>

#define BATCH 64
#define LSUB  512
#define SWORDS 512
#define HID   768
#define NC    9
#define NWORDS (BATCH * SWORDS)

__device__ int   g_starts[NWORDS];
__device__ float g_loss;
__device__ int   g_cnt;

// ---------------------------------------------------------------------------
// Kernel A: one WARP per batch. Each lane owns 16 contiguous words, computes a
// serial local exclusive prefix, then a warp shfl-scan of the lane totals.
// No __syncthreads at all.
// ---------------------------------------------------------------------------
__global__ void scan_kernel(const int* __restrict__ ids_lens) {
    int b = blockIdx.x, lane = threadIdx.x;
    int base = b * SWORDS + lane * 16;

    const int4* p = (const int4*)(ids_lens + base);
    int4 q[4];
#pragma unroll
    for (int i = 0; i < 4; i++) q[i] = p[i];

    int v[16];
#pragma unroll
    for (int i = 0; i < 4; i++) {
        v[i*4+0] = ((const int*)&q[i])[0];
        v[i*4+1] = ((const int*)&q[i])[1];
        v[i*4+2] = ((const int*)&q[i])[2];
        v[i*4+3] = ((const int*)&q[i])[3];
    }

    int ex[16], run = 0;
#pragma unroll
    for (int i = 0; i < 16; i++) { ex[i] = run; run += v[i]; }

    // inclusive warp scan of per-lane totals
    int inc = run;
#pragma unroll
    for (int off = 1; off < 32; off <<= 1) {
        int n = __shfl_up_sync(0xffffffffu, inc, off);
        if (lane >= off) inc += n;
    }
    int lane_ex = inc - run;

    int4* outp = (int4*)(g_starts + base);
#pragma unroll
    for (int i = 0; i < 4; i++) {
        int4 o;
        ((int*)&o)[0] = lane_ex + ex[i*4+0];
        ((int*)&o)[1] = lane_ex + ex[i*4+1];
        ((int*)&o)[2] = lane_ex + ex[i*4+2];
        ((int*)&o)[3] = lane_ex + ex[i*4+3];
        outp[i] = o;
    }
    if (b == 0 && lane == 0) { g_loss = 0.0f; g_cnt = 0; }
}

// ---------------------------------------------------------------------------
// Kernel B: one warp handles 2 words per iteration. Float4 loads along H,
// fully-unrolled PREDICATED row loads (len in {0..3}), W transposed [C][H]
// in shared (LDS.128, conflict-free).
// ---------------------------------------------------------------------------
__global__ void __launch_bounds__(256) main_kernel(
    const float* __restrict__ x,
    const float* __restrict__ W,
    const float* __restrict__ bias,
    const int*   __restrict__ ids_lens,
    const int*   __restrict__ label_ids,
    float*       __restrict__ out)
{
    __shared__ float Ws[NC * HID];     // transposed: Ws[c*HID + h]
    __shared__ float sb[NC];
    __shared__ float s_loss;
    __shared__ int   s_cnt;

    int tid = threadIdx.x;
    for (int i = tid; i < HID * NC; i += blockDim.x) {
        int h = i / NC, c = i % NC;
        Ws[c * HID + h] = W[i];
    }
    if (tid < NC) sb[tid] = bias[tid];
    if (tid == 0) { s_loss = 0.0f; s_cnt = 0; }
    __syncthreads();

    int lane = tid & 31;
    int warp = tid >> 5;
    int gw   = blockIdx.x * (blockDim.x >> 5) + warp;
    int nw   = gridDim.x * (blockDim.x >> 5);

    float lloss = 0.0f;
    int   lcnt  = 0;

    for (int p = gw; p < NWORDS / 2; p += nw) {
        int w0 = 2 * p, w1 = 2 * p + 1;          // same batch (w0 even)
        int len0 = ids_lens[w0], len1 = ids_lens[w1];
        int st0  = g_starts[w0], st1 = g_starts[w1];
        int b0   = w0 >> 9;

        const float4* base0 = (const float4*)(x + ((size_t)(b0 * LSUB + st0)) * HID);
        const float4* base1 = (const float4*)(x + ((size_t)(b0 * LSUB + st1)) * HID);
        const int RS = HID / 4;                  // row stride in float4 = 192

        float acc0[NC], acc1[NC];
#pragma unroll
        for (int c = 0; c < NC; c++) { acc0[c] = 0.0f; acc1[c] = 0.0f; }

        const float4 z = make_float4(0.f, 0.f, 0.f, 0.f);

#pragma unroll
        for (int g = 0; g < 6; g++) {
            int idx = g * 32 + lane;             // float4 index within a row
            float4 a0 = (len0 > 0) ? base0[idx]          : z;
            float4 a1 = (len0 > 1) ? base0[idx + RS]     : z;
            float4 a2 = (len0 > 2) ? base0[idx + 2*RS]   : z;
            float4 c0 = (len1 > 0) ? base1[idx]          : z;
            float4 c1 = (len1 > 1) ? base1[idx + RS]     : z;
            float4 c2 = (len1 > 2) ? base1[idx + 2*RS]   : z;

            float4 v0 = make_float4(a0.x + a1.x + a2.x, a0.y + a1.y + a2.y,
                                    a0.z + a1.z + a2.z, a0.w + a1.w + a2.w);
            float4 v1 = make_float4(c0.x + c1.x + c2.x, c0.y + c1.y + c2.y,
                                    c0.z + c1.z + c2.z, c0.w + c1.w + c2.w);

            int hb = g * 128 + lane * 4;
#pragma unroll
            for (int c = 0; c < NC; c++) {
                float4 wc = *(const float4*)&Ws[c * HID + hb];
                acc0[c] = fmaf(v0.x, wc.x, fmaf(v0.y, wc.y,
                          fmaf(v0.z, wc.z, fmaf(v0.w, wc.w, acc0[c]))));
                acc1[c] = fmaf(v1.x, wc.x, fmaf(v1.y, wc.y,
                          fmaf(v1.z, wc.z, fmaf(v1.w, wc.w, acc1[c]))));
            }
        }

#pragma unroll
        for (int c = 0; c < NC; c++) {
#pragma unroll
            for (int off = 16; off; off >>= 1) {
                acc0[c] += __shfl_xor_sync(0xffffffffu, acc0[c], off);
                acc1[c] += __shfl_xor_sync(0xffffffffu, acc1[c], off);
            }
        }

        if (lane == 0) {
#pragma unroll
            for (int which = 0; which < 2; which++) {
                int   w   = which ? w1 : w0;
                int   len = which ? len1 : len0;
                float* a  = which ? acc1 : acc0;

                float inv = (len > 0) ? (1.0f / (float)len) : 0.0f;
                float lg[NC];
                float m = -1e30f; int am = 0;
#pragma unroll
                for (int c = 0; c < NC; c++) {
                    lg[c] = fmaf(a[c], inv, sb[c]);
                    if (lg[c] > m) { m = lg[c]; am = c; }
                }
                out[1 + w] = (float)am;
                if (len > 0) {
                    float sum = 0.0f;
#pragma unroll
                    for (int c = 0; c < NC; c++) sum += __expf(lg[c] - m);
                    int lab = label_ids[w];
                    lab = lab < 0 ? 0 : (lab > NC - 1 ? NC - 1 : lab);
                    lloss += -(lg[lab] - m - __logf(sum));
                    lcnt  += 1;
                }
            }
        }
    }

    if (lane == 0 && lcnt > 0) {
        atomicAdd(&s_loss, lloss);
        atomicAdd(&s_cnt, lcnt);
    }
    __syncthreads();
    if (tid == 0 && s_cnt > 0) {
        atomicAdd(&g_loss, s_loss);
        atomicAdd(&g_cnt, s_cnt);
    }
}

__global__ void finalize_kernel(float* __restrict__ out) {
    out[0] = g_loss / fmaxf((float)g_cnt, 1.0f);
}

extern "C" void kernel_launch(void* const* d_in, const int* in_sizes, int n_in,
                              void* d_out, int out_size) {
    const float* bert_out  = (const float*)d_in[0];
    const float* W         = (const float*)d_in[1];
    const float* b         = (const float*)d_in[2];
    const int*   ids_lens  = (const int*)d_in[4];
    const int*   label_ids = (const int*)d_in[5];
    float* out = (float*)d_out;

    scan_kernel<<<BATCH, 32>>>(ids_lens);
    main_kernel<<<592, 256>>>(bert_out, W, b, ids_lens, label_ids, out);
    finalize_kernel<<<1, 1>>>(out);
}